// round 7
// baseline (speedup 1.0000x reference)
#include <cuda_runtime.h>
#include <cuda_fp16.h>
#include <math.h>
#include <stdint.h>

// ============================================================================
// LSTM cell, fp16 mma.sync.m16n8k16, warp tile m64 x n64 (high LDS reuse).
//   prep_A: fp16-rn convert [x|h]        -> g_Ah  [m][k]   (K-major)
//   prep_W: transpose + fp16-rn weights  -> g_Wh  [g][n][k] (K-major)
//   main:   CTA tile BM=128 x (4 gates x 64), 8 warps = 4 gates x 2 m-halves,
//           each warp m64 x n64, BK=64, 3-stage cp.async ring, ldmatrix.x4,
//           fused sigmoid/tanh epilogue -> out = [hy ; cy]
// ============================================================================

#define MDIM 4096
#define NDIM 2048
#define KDIM 4096
#define BM 128
#define BN 64                 // per gate
#define BK 64                 // 128B rows
#define KT (KDIM / BK)        // 64
#define THREADS 256
#define STAGES 3

#define A_STAGE_BYTES  (BM * 128)            // 16384
#define BG_STAGE_BYTES (BN * 128)            // 8192 per gate
#define STAGE_BYTES    (A_STAGE_BYTES + 4 * BG_STAGE_BYTES)   // 49152
#define SMEM_TOTAL     (STAGES * STAGE_BYTES)                 // 147456

#define SWZ(o) ((o) ^ (((o) >> 3) & 0x70))

__device__ uint4 g_Ah4[(size_t)MDIM * KDIM / 8];        // fp16 [m][k]
__device__ uint4 g_Wh4[(size_t)4 * NDIM * KDIM / 8];    // fp16 [g][n][k]

// ------------------------------ helpers ------------------------------------
__device__ __forceinline__ uint32_t smem_u32_of(const void* p) {
    uint32_t a;
    asm("{ .reg .u64 t; cvta.to.shared.u64 t, %1; cvt.u32.u64 %0, t; }" : "=r"(a) : "l"(p));
    return a;
}

#define CP_ASYNC16(dst, src) \
    asm volatile("cp.async.cg.shared.global [%0], [%1], 16;" :: "r"(dst), "l"(src) : "memory")
#define CP_COMMIT()  asm volatile("cp.async.commit_group;" ::: "memory")
#define CP_WAIT2()   asm volatile("cp.async.wait_group 2;" ::: "memory")

#define LDSM_X4(d, addr) \
    asm volatile("ldmatrix.sync.aligned.m8n8.x4.shared.b16 {%0,%1,%2,%3}, [%4];" \
        : "=r"((d)[0]), "=r"((d)[1]), "=r"((d)[2]), "=r"((d)[3]) : "r"(addr))

__device__ __forceinline__ void mma16816(float c[4], const uint32_t a[4],
                                         uint32_t b0, uint32_t b1) {
    asm volatile(
        "mma.sync.aligned.m16n8k16.row.col.f32.f16.f16.f32 "
        "{%0,%1,%2,%3}, {%4,%5,%6,%7}, {%8,%9}, {%0,%1,%2,%3};\n"
        : "+f"(c[0]), "+f"(c[1]), "+f"(c[2]), "+f"(c[3])
        : "r"(a[0]), "r"(a[1]), "r"(a[2]), "r"(a[3]), "r"(b0), "r"(b1));
}

// ------------------------------ pre-passes ---------------------------------
__global__ void prep_A(const float* __restrict__ x, const float* __restrict__ h) {
    const size_t idx = (size_t)blockIdx.x * blockDim.x + threadIdx.x;
    const int m = (int)(idx >> 9);
    const int k = (int)(idx & 511) * 8;
    const float* s = (k < 2048) ? x + (size_t)m * 2048 + k
                                : h + (size_t)m * 2048 + (k - 2048);
    const float4 v0 = ((const float4*)s)[0];
    const float4 v1 = ((const float4*)s)[1];
    __half2 p0 = __floats2half2_rn(v0.x, v0.y);
    __half2 p1 = __floats2half2_rn(v0.z, v0.w);
    __half2 p2 = __floats2half2_rn(v1.x, v1.y);
    __half2 p3 = __floats2half2_rn(v1.z, v1.w);
    uint4 o;
    o.x = *(uint32_t*)&p0; o.y = *(uint32_t*)&p1;
    o.z = *(uint32_t*)&p2; o.w = *(uint32_t*)&p3;
    g_Ah4[idx] = o;
}

__global__ void prep_W(const float* Wxi, const float* Whi, const float* Wxf, const float* Whf,
                       const float* Wxc, const float* Whc, const float* Wxo, const float* Who) {
    __shared__ float t[32][33];
    const float* Wx[4] = {Wxi, Wxf, Wxc, Wxo};
    const float* Wh[4] = {Whi, Whf, Whc, Who};
    const int g  = blockIdx.z;
    const int k0 = blockIdx.x * 32, n0 = blockIdx.y * 32;
    const float* src = (k0 < 2048) ? Wx[g] : Wh[g];
    const int kk = k0 & 2047;
    const int tx = threadIdx.x, ty = threadIdx.y;
    __half* gW = (__half*)g_Wh4;
#pragma unroll
    for (int j = 0; j < 4; j++)
        t[ty + 8 * j][tx] = src[(size_t)(kk + ty + 8 * j) * NDIM + n0 + tx];
    __syncthreads();
#pragma unroll
    for (int j = 0; j < 4; j++)
        gW[((size_t)g * NDIM + n0 + ty + 8 * j) * KDIM + k0 + tx] =
            __float2half_rn(t[tx][ty + 8 * j]);
}

// ------------------------------ main kernel --------------------------------
__device__ __forceinline__ void load_stage(uint32_t st, int kb, int tid, int bm, int bn) {
    const __half* gA = (const __half*)g_Ah4;
    const __half* gW = (const __half*)g_Wh4;
#pragma unroll
    for (int i = 0; i < 12; i++) {
        const int ch = tid + i * 256;                 // 0..3071
        if (ch < 1024) {                              // A: 128 rows x 8 chunks
            const int row = ch >> 3, c16 = ch & 7;
            const __half* src = gA + (size_t)(bm + row) * KDIM + kb + c16 * 8;
            CP_ASYNC16(st + SWZ(row * 128 + c16 * 16), src);
        } else {                                      // B: 4 gates x 64 rows x 8
            const int b = ch - 1024;
            const int gg = b >> 9, bb = b & 511;
            const int row = bb >> 3, c16 = bb & 7;
            const __half* src = gW + ((size_t)gg * NDIM + bn + row) * KDIM + kb + c16 * 8;
            CP_ASYNC16(st + A_STAGE_BYTES + gg * BG_STAGE_BYTES + SWZ(row * 128 + c16 * 16), src);
        }
    }
    CP_COMMIT();
}

__global__ __launch_bounds__(THREADS, 1)
void lstm_fp16_kernel(const float* __restrict__ cx,
                      const float* __restrict__ bi, const float* __restrict__ bf_,
                      const float* __restrict__ bc, const float* __restrict__ bo,
                      float* __restrict__ out) {
    extern __shared__ char smem[];
    const uint32_t sbase = smem_u32_of(smem);

    const int tid  = threadIdx.x;
    const int lane = tid & 31;
    const int wid  = tid >> 5;
    const int g    = wid & 3;    // gate
    const int mh   = wid >> 2;   // m-half (rows 0-63 / 64-127)

    const int bn = blockIdx.x * BN;
    const int bm = blockIdx.y * BM;

    float acc[4][8][4];
#pragma unroll
    for (int t = 0; t < 4; t++)
#pragma unroll
        for (int j = 0; j < 8; j++)
#pragma unroll
            for (int q = 0; q < 4; q++) acc[t][j][q] = 0.0f;

    // per-lane ldmatrix geometry
    const int j8    = lane & 7;
    const int mm    = lane >> 3;
    const int mlo   = (mm & 1) * 8;
    const int khalf = (mm >> 1) * 16;
    const int S     = j8 << 4;
    const int rowA  = mh * 64 + mlo + j8;   // + 16*t
    const int rowB  = mlo + j8;             // + 16*p

    // prologue: fill all three stages
    load_stage(sbase, 0, tid, bm, bn);
    load_stage(sbase + STAGE_BYTES, BK, tid, bm, bn);
    load_stage(sbase + 2 * STAGE_BYTES, 2 * BK, tid, bm, bn);

    int slot = 0;
    for (int kt = 0; kt < KT; kt++) {
        CP_WAIT2();
        __syncthreads();

        const uint32_t stA = sbase + slot * STAGE_BYTES;
        const uint32_t stB = stA + A_STAGE_BYTES + g * BG_STAGE_BYTES;

#pragma unroll
        for (int ks = 0; ks < 4; ks++) {
            const int KX = (ks * 32 + khalf) ^ S;
            uint32_t a[4][4], b[4][4];
#pragma unroll
            for (int t = 0; t < 4; t++)
                LDSM_X4(a[t], stA + (rowA + t * 16) * 128 + KX);
#pragma unroll
            for (int p = 0; p < 4; p++)
                LDSM_X4(b[p], stB + (rowB + p * 16) * 128 + KX);
#pragma unroll
            for (int t = 0; t < 4; t++)
#pragma unroll
                for (int j = 0; j < 8; j++) {
                    const int p = j >> 1, o = j & 1;
                    mma16816(acc[t][j], a[t], b[p][o], b[p][o + 2]);
                }
        }
        __syncthreads();

        if (kt + STAGES < KT) load_stage(sbase + slot * STAGE_BYTES, (kt + STAGES) * BK, tid, bm, bn);
        else                  CP_COMMIT();   // keep outstanding-group invariant
        slot = (slot == STAGES - 1) ? 0 : slot + 1;
    }

    // ---- epilogue: combine gates, activations, write hy/cy ----
    float* eps = (float*)smem;                 // [4][64][64] = 64 KB
    const size_t outCY = (size_t)MDIM * NDIM;
    const int r = lane >> 2;
    const int c = lane & 3;

#pragma unroll
    for (int ph = 0; ph < 2; ph++) {
        __syncthreads();
        if (mh == ph) {
#pragma unroll
            for (int t = 0; t < 4; t++) {
#pragma unroll
                for (int j = 0; j < 8; j++) {
                    const int row0 = t * 16 + r;
                    const int col0 = j * 8 + c * 2;
                    eps[(g * 64 + row0) * 64 + col0]         = acc[t][j][0];
                    eps[(g * 64 + row0) * 64 + col0 + 1]     = acc[t][j][1];
                    eps[(g * 64 + row0 + 8) * 64 + col0]     = acc[t][j][2];
                    eps[(g * 64 + row0 + 8) * 64 + col0 + 1] = acc[t][j][3];
                }
            }
        }
        __syncthreads();

        for (int idx = tid; idx < 64 * 64; idx += THREADS) {
            const int ml = idx >> 6;
            const int nl = idx & 63;
            const int gm = bm + ph * 64 + ml;
            const int gn = bn + nl;

            const float zi = eps[(0 * 64 + ml) * 64 + nl] + bi[gn];
            const float zf = eps[(1 * 64 + ml) * 64 + nl] + bf_[gn];
            const float zc = eps[(2 * 64 + ml) * 64 + nl] + bc[gn];
            const float zo = eps[(3 * 64 + ml) * 64 + nl] + bo[gn];

            const float ig = 1.0f / (1.0f + expf(-zi));
            const float fg = 1.0f / (1.0f + expf(-zf));
            const float og = 1.0f / (1.0f + expf(-zo));
            const float ct = tanhf(zc);

            const float cprev = cx[(size_t)gm * NDIM + gn];
            const float cy = fg * cprev + ig * ct;
            const float hy = og * tanhf(cy);

            out[(size_t)gm * NDIM + gn] = hy;
            out[outCY + (size_t)gm * NDIM + gn] = cy;
        }
    }
}

// ------------------------------- launch ------------------------------------
extern "C" void kernel_launch(void* const* d_in, const int* in_sizes, int n_in,
                              void* d_out, int out_size) {
    (void)in_sizes; (void)n_in; (void)out_size;
    cudaFuncSetAttribute(lstm_fp16_kernel,
                         cudaFuncAttributeMaxDynamicSharedMemorySize, SMEM_TOTAL);

    prep_A<<<8192, 256>>>((const float*)d_in[0], (const float*)d_in[1]);
    prep_W<<<dim3(KDIM / 32, NDIM / 32, 4), dim3(32, 8)>>>(
        (const float*)d_in[3],  (const float*)d_in[4],    // W_xi, W_hi
        (const float*)d_in[6],  (const float*)d_in[7],    // W_xf, W_hf
        (const float*)d_in[9],  (const float*)d_in[10],   // W_xc, W_hc
        (const float*)d_in[12], (const float*)d_in[13]);  // W_xo, W_ho

    dim3 grid(NDIM / BN, MDIM / BM);   // 32 x 32 = 1024 CTAs
    lstm_fp16_kernel<<<grid, THREADS, SMEM_TOTAL>>>(
        (const float*)d_in[2],                           // c_x
        (const float*)d_in[5],  (const float*)d_in[8],   // b_i, b_f
        (const float*)d_in[11], (const float*)d_in[14],  // b_c, b_o
        (float*)d_out);
}

// round 10
// speedup vs baseline: 1.1348x; 1.1348x over previous
#include <cuda_runtime.h>
#include <cuda_fp16.h>
#include <math.h>
#include <stdint.h>

// ============================================================================
// LSTM cell, fp16 mma.sync.m16n8k16, 512 threads, 16 warps = 4 gates x 4
// m-quarters (warp tile m32 x n64), BM=128, 4-stage cp.async ring with a
// single __syncthreads per K-stage (CUTLASS multistage discipline).
//   prep_A: fp16-rn convert [x|h]        -> g_Ah  [m][k]   (K-major)
//   prep_W: transpose + fp16-rn weights  -> g_Wh  [g][n][k] (K-major)
// ============================================================================

#define MDIM 4096
#define NDIM 2048
#define KDIM 4096
#define BM 128
#define BN 64                 // per gate
#define BK 64                 // 128B rows
#define KT (KDIM / BK)        // 64
#define THREADS 512
#define STAGES 4

#define A_STAGE_BYTES  (BM * 128)            // 16384
#define BG_STAGE_BYTES (BN * 128)            // 8192 per gate
#define STAGE_BYTES    (A_STAGE_BYTES + 4 * BG_STAGE_BYTES)   // 49152
#define SMEM_TOTAL     (STAGES * STAGE_BYTES)                 // 196608

#define SWZ(o) ((o) ^ (((o) >> 3) & 0x70))

__device__ uint4 g_Ah4[(size_t)MDIM * KDIM / 8];        // fp16 [m][k]
__device__ uint4 g_Wh4[(size_t)4 * NDIM * KDIM / 8];    // fp16 [g][n][k]

// ------------------------------ helpers ------------------------------------
__device__ __forceinline__ uint32_t smem_u32_of(const void* p) {
    uint32_t a;
    asm("{ .reg .u64 t; cvta.to.shared.u64 t, %1; cvt.u32.u64 %0, t; }" : "=r"(a) : "l"(p));
    return a;
}

#define CP_ASYNC16(dst, src) \
    asm volatile("cp.async.cg.shared.global [%0], [%1], 16;" :: "r"(dst), "l"(src) : "memory")
#define CP_COMMIT()  asm volatile("cp.async.commit_group;" ::: "memory")
#define CP_WAIT2()   asm volatile("cp.async.wait_group 2;" ::: "memory")

#define LDSM_X4(d, addr) \
    asm volatile("ldmatrix.sync.aligned.m8n8.x4.shared.b16 {%0,%1,%2,%3}, [%4];" \
        : "=r"((d)[0]), "=r"((d)[1]), "=r"((d)[2]), "=r"((d)[3]) : "r"(addr))

__device__ __forceinline__ void mma16816(float c[4], const uint32_t a[4],
                                         uint32_t b0, uint32_t b1) {
    asm volatile(
        "mma.sync.aligned.m16n8k16.row.col.f32.f16.f16.f32 "
        "{%0,%1,%2,%3}, {%4,%5,%6,%7}, {%8,%9}, {%0,%1,%2,%3};\n"
        : "+f"(c[0]), "+f"(c[1]), "+f"(c[2]), "+f"(c[3])
        : "r"(a[0]), "r"(a[1]), "r"(a[2]), "r"(a[3]), "r"(b0), "r"(b1));
}

// ------------------------------ pre-passes ---------------------------------
__global__ void prep_A(const float* __restrict__ x, const float* __restrict__ h) {
    const size_t idx = (size_t)blockIdx.x * blockDim.x + threadIdx.x;
    const int m = (int)(idx >> 9);
    const int k = (int)(idx & 511) * 8;
    const float* s = (k < 2048) ? x + (size_t)m * 2048 + k
                                : h + (size_t)m * 2048 + (k - 2048);
    const float4 v0 = ((const float4*)s)[0];
    const float4 v1 = ((const float4*)s)[1];
    __half2 p0 = __floats2half2_rn(v0.x, v0.y);
    __half2 p1 = __floats2half2_rn(v0.z, v0.w);
    __half2 p2 = __floats2half2_rn(v1.x, v1.y);
    __half2 p3 = __floats2half2_rn(v1.z, v1.w);
    uint4 o;
    o.x = *(uint32_t*)&p0; o.y = *(uint32_t*)&p1;
    o.z = *(uint32_t*)&p2; o.w = *(uint32_t*)&p3;
    g_Ah4[idx] = o;
}

__global__ void prep_W(const float* Wxi, const float* Whi, const float* Wxf, const float* Whf,
                       const float* Wxc, const float* Whc, const float* Wxo, const float* Who) {
    __shared__ float t[32][33];
    const float* Wx[4] = {Wxi, Wxf, Wxc, Wxo};
    const float* Wh[4] = {Whi, Whf, Whc, Who};
    const int g  = blockIdx.z;
    const int k0 = blockIdx.x * 32, n0 = blockIdx.y * 32;
    const float* src = (k0 < 2048) ? Wx[g] : Wh[g];
    const int kk = k0 & 2047;
    const int tx = threadIdx.x, ty = threadIdx.y;
    __half* gW = (__half*)g_Wh4;
#pragma unroll
    for (int j = 0; j < 4; j++)
        t[ty + 8 * j][tx] = src[(size_t)(kk + ty + 8 * j) * NDIM + n0 + tx];
    __syncthreads();
#pragma unroll
    for (int j = 0; j < 4; j++)
        gW[((size_t)g * NDIM + n0 + ty + 8 * j) * KDIM + k0 + tx] =
            __float2half_rn(t[tx][ty + 8 * j]);
}

// ------------------------------ main kernel --------------------------------
__device__ __forceinline__ void load_stage(uint32_t st, int kb, int tid, int bm, int bn) {
    const __half* gA = (const __half*)g_Ah4;
    const __half* gW = (const __half*)g_Wh4;
#pragma unroll
    for (int i = 0; i < 6; i++) {
        const int ch = tid + i * 512;                 // 0..3071
        if (ch < 1024) {                              // A: 128 rows x 8 chunks
            const int row = ch >> 3, c16 = ch & 7;
            const __half* src = gA + (size_t)(bm + row) * KDIM + kb + c16 * 8;
            CP_ASYNC16(st + SWZ(row * 128 + c16 * 16), src);
        } else {                                      // B: 4 gates x 64 rows x 8
            const int b = ch - 1024;
            const int gg = b >> 9, bb = b & 511;
            const int row = bb >> 3, c16 = bb & 7;
            const __half* src = gW + ((size_t)gg * NDIM + bn + row) * KDIM + kb + c16 * 8;
            CP_ASYNC16(st + A_STAGE_BYTES + gg * BG_STAGE_BYTES + SWZ(row * 128 + c16 * 16), src);
        }
    }
    CP_COMMIT();
}

__global__ __launch_bounds__(THREADS, 1)
void lstm_fp16_kernel(const float* __restrict__ cx,
                      const float* __restrict__ bi, const float* __restrict__ bf_,
                      const float* __restrict__ bc, const float* __restrict__ bo,
                      float* __restrict__ out) {
    extern __shared__ char smem[];
    const uint32_t sbase = smem_u32_of(smem);

    const int tid  = threadIdx.x;
    const int lane = tid & 31;
    const int wid  = tid >> 5;
    const int g    = wid & 3;    // gate
    const int mq   = wid >> 2;   // m-quarter (32 rows each)

    const int bn = blockIdx.x * BN;
    const int bm = blockIdx.y * BM;

    float acc[2][8][4];
#pragma unroll
    for (int t = 0; t < 2; t++)
#pragma unroll
        for (int j = 0; j < 8; j++)
#pragma unroll
            for (int q = 0; q < 4; q++) acc[t][j][q] = 0.0f;

    // per-lane ldmatrix geometry
    const int j8    = lane & 7;
    const int mm    = lane >> 3;
    const int mlo   = (mm & 1) * 8;
    const int khalf = (mm >> 1) * 16;
    const int S     = j8 << 4;
    const int rowA  = mq * 32 + mlo + j8;   // + 16*t
    const int rowB  = mlo + j8;             // + 16*p

    // prologue: fill 3 of 4 stages
    load_stage(sbase, 0, tid, bm, bn);
    load_stage(sbase + STAGE_BYTES, BK, tid, bm, bn);
    load_stage(sbase + 2 * STAGE_BYTES, 2 * BK, tid, bm, bn);

    for (int kt = 0; kt < KT; kt++) {
        CP_WAIT2();
        __syncthreads();

        // issue loads for stage kt+3 into slot (kt+3)&3 == slot read at kt-1
        if (kt + 3 < KT) load_stage(sbase + ((kt + 3) & 3) * STAGE_BYTES,
                                    (kt + 3) * BK, tid, bm, bn);
        else             CP_COMMIT();   // keep outstanding-group invariant

        const uint32_t stA = sbase + (kt & 3) * STAGE_BYTES;
        const uint32_t stB = stA + A_STAGE_BYTES + g * BG_STAGE_BYTES;

#pragma unroll
        for (int ks = 0; ks < 4; ks++) {
            const int KX = (ks * 32 + khalf) ^ S;
            uint32_t a[2][4], b[4][4];
#pragma unroll
            for (int t = 0; t < 2; t++)
                LDSM_X4(a[t], stA + (rowA + t * 16) * 128 + KX);
#pragma unroll
            for (int p = 0; p < 4; p++)
                LDSM_X4(b[p], stB + (rowB + p * 16) * 128 + KX);
#pragma unroll
            for (int t = 0; t < 2; t++)
#pragma unroll
                for (int j = 0; j < 8; j++) {
                    const int p = j >> 1, o = j & 1;
                    mma16816(acc[t][j], a[t], b[p][o], b[p][o + 2]);
                }
        }
    }

    // ---- epilogue: single pass, all 16 warps ----
    __syncthreads();
    float* eps = (float*)smem;                 // [4][128][64] = 128 KB
    const size_t outCY = (size_t)MDIM * NDIM;
    const int r = lane >> 2;
    const int c = lane & 3;

#pragma unroll
    for (int t = 0; t < 2; t++) {
#pragma unroll
        for (int j = 0; j < 8; j++) {
            const int row0 = mq * 32 + t * 16 + r;
            const int col0 = j * 8 + c * 2;
            eps[(g * 128 + row0) * 64 + col0]         = acc[t][j][0];
            eps[(g * 128 + row0) * 64 + col0 + 1]     = acc[t][j][1];
            eps[(g * 128 + row0 + 8) * 64 + col0]     = acc[t][j][2];
            eps[(g * 128 + row0 + 8) * 64 + col0 + 1] = acc[t][j][3];
        }
    }
    __syncthreads();

    for (int idx4 = tid; idx4 < 128 * 16; idx4 += THREADS) {
        const int ml  = idx4 >> 4;
        const int nl4 = (idx4 & 15) * 4;
        const int gm  = bm + ml;
        const int gn  = bn + nl4;

        const float4 vi4 = *(const float4*)(eps + (0 * 128 + ml) * 64 + nl4);
        const float4 vf4 = *(const float4*)(eps + (1 * 128 + ml) * 64 + nl4);
        const float4 vc4 = *(const float4*)(eps + (2 * 128 + ml) * 64 + nl4);
        const float4 vo4 = *(const float4*)(eps + (3 * 128 + ml) * 64 + nl4);
        const float4 cp4 = *(const float4*)(cx + (size_t)gm * NDIM + gn);
        const float4 bi4 = *(const float4*)(bi + gn);
        const float4 bf4 = *(const float4*)(bf_ + gn);
        const float4 bc4 = *(const float4*)(bc + gn);
        const float4 bo4 = *(const float4*)(bo + gn);

        float hy[4], cyv[4];
        const float* vi = &vi4.x; const float* vf = &vf4.x;
        const float* vc = &vc4.x; const float* vo = &vo4.x;
        const float* cp = &cp4.x;
        const float* pbi = &bi4.x; const float* pbf = &bf4.x;
        const float* pbc = &bc4.x; const float* pbo = &bo4.x;
#pragma unroll
        for (int q = 0; q < 4; q++) {
            const float zi = vi[q] + pbi[q];
            const float zf = vf[q] + pbf[q];
            const float zc = vc[q] + pbc[q];
            const float zo = vo[q] + pbo[q];
            const float ig = 1.0f / (1.0f + expf(-zi));
            const float fg = 1.0f / (1.0f + expf(-zf));
            const float og = 1.0f / (1.0f + expf(-zo));
            const float ct = tanhf(zc);
            cyv[q] = fg * cp[q] + ig * ct;
            hy[q]  = og * tanhf(cyv[q]);
        }
        *(float4*)(out + (size_t)gm * NDIM + gn) = make_float4(hy[0], hy[1], hy[2], hy[3]);
        *(float4*)(out + outCY + (size_t)gm * NDIM + gn) = make_float4(cyv[0], cyv[1], cyv[2], cyv[3]);
    }
}

// ------------------------------- launch ------------------------------------
extern "C" void kernel_launch(void* const* d_in, const int* in_sizes, int n_in,
                              void* d_out, int out_size) {
    (void)in_sizes; (void)n_in; (void)out_size;
    cudaFuncSetAttribute(lstm_fp16_kernel,
                         cudaFuncAttributeMaxDynamicSharedMemorySize, SMEM_TOTAL);

    prep_A<<<8192, 256>>>((const float*)d_in[0], (const float*)d_in[1]);
    prep_W<<<dim3(KDIM / 32, NDIM / 32, 4), dim3(32, 8)>>>(
        (const float*)d_in[3],  (const float*)d_in[4],    // W_xi, W_hi
        (const float*)d_in[6],  (const float*)d_in[7],    // W_xf, W_hf
        (const float*)d_in[9],  (const float*)d_in[10],   // W_xc, W_hc
        (const float*)d_in[12], (const float*)d_in[13]);  // W_xo, W_ho

    dim3 grid(NDIM / BN, MDIM / BM);   // 32 x 32 = 1024 CTAs
    lstm_fp16_kernel<<<grid, THREADS, SMEM_TOTAL>>>(
        (const float*)d_in[2],                           // c_x
        (const float*)d_in[5],  (const float*)d_in[8],   // b_i, b_f
        (const float*)d_in[11], (const float*)d_in[14],  // b_c, b_o
        (float*)d_out);
}

// round 13
// speedup vs baseline: 1.2647x; 1.1145x over previous
#include <cuda_runtime.h>
#include <cuda_fp16.h>
#include <math.h>
#include <stdint.h>

// ============================================================================
// LSTM cell, fp16 mma.sync.m16n8k16 (sm_103 base target — no tcgen05).
//   prep:  fp16-rn convert [x|h] -> g_Ah [m][k]; transpose+convert weights
//          -> g_Wh [g][n][k]   (single fused launch)
//   main:  BM64 x (4 gates x 64) tile, 8 warps = 4 gates x 2 m-halves,
//          BK=64, 2-stage cp.async ring with EARLY load issue (loads for
//          stage kt+2 issued before compute of stage kt), ldmatrix.x4,
//          fast-math fused sigmoid/tanh epilogue -> out = [hy ; cy]
// ============================================================================

#define MDIM 4096
#define NDIM 2048
#define KDIM 4096
#define BM 64
#define BN 64                 // per gate
#define BK 64                 // 128B rows
#define KT (KDIM / BK)        // 64
#define THREADS 256

#define A_STAGE_BYTES  (BM * 128)            // 8192
#define BG_STAGE_BYTES (BN * 128)            // 8192 per gate
#define STAGE_BYTES    (A_STAGE_BYTES + 4 * BG_STAGE_BYTES)   // 40960
#define SMEM_TOTAL     (2 * STAGE_BYTES)                      // 81920

#define SWZ(o) ((o) ^ (((o) >> 3) & 0x70))

__device__ uint4 g_Ah4[(size_t)MDIM * KDIM / 8];        // fp16 [m][k]
__device__ uint4 g_Wh4[(size_t)4 * NDIM * KDIM / 8];    // fp16 [g][n][k]

// ------------------------------ helpers ------------------------------------
__device__ __forceinline__ uint32_t smem_u32_of(const void* p) {
    uint32_t a;
    asm("{ .reg .u64 t; cvta.to.shared.u64 t, %1; cvt.u32.u64 %0, t; }" : "=r"(a) : "l"(p));
    return a;
}

#define CP_ASYNC16(dst, src) \
    asm volatile("cp.async.cg.shared.global [%0], [%1], 16;" :: "r"(dst), "l"(src) : "memory")
#define CP_COMMIT()  asm volatile("cp.async.commit_group;" ::: "memory")
#define CP_WAIT1()   asm volatile("cp.async.wait_group 1;" ::: "memory")

#define LDSM_X4(d, addr) \
    asm volatile("ldmatrix.sync.aligned.m8n8.x4.shared.b16 {%0,%1,%2,%3}, [%4];" \
        : "=r"((d)[0]), "=r"((d)[1]), "=r"((d)[2]), "=r"((d)[3]) : "r"(addr))

__device__ __forceinline__ void mma16816(float c[4], const uint32_t a[4],
                                         uint32_t b0, uint32_t b1) {
    asm volatile(
        "mma.sync.aligned.m16n8k16.row.col.f32.f16.f16.f32 "
        "{%0,%1,%2,%3}, {%4,%5,%6,%7}, {%8,%9}, {%0,%1,%2,%3};\n"
        : "+f"(c[0]), "+f"(c[1]), "+f"(c[2]), "+f"(c[3])
        : "r"(a[0]), "r"(a[1]), "r"(a[2]), "r"(a[3]), "r"(b0), "r"(b1));
}

__device__ __forceinline__ float fast_tanh(float x) {
    float r;
    asm("tanh.approx.f32 %0, %1;" : "=f"(r) : "f"(x));
    return r;
}
__device__ __forceinline__ float fast_sigmoid(float x) {
    return 1.0f / (1.0f + __expf(-x));
}

// ------------------------------ fused pre-pass -----------------------------
// gridDim.x = 8192 + 8192 blocks of 256 threads.
//  blocks [0, 8192)      : A conversion (as before)
//  blocks [8192, 16384)  : weight transpose — each block does a 32x32 tile
//                          for all 4 gates sequentially (blocks map k0 x n0).
__global__ void prep_all(const float* __restrict__ x, const float* __restrict__ h,
                         const float* __restrict__ Wxi, const float* __restrict__ Whi,
                         const float* __restrict__ Wxf, const float* __restrict__ Whf,
                         const float* __restrict__ Wxc, const float* __restrict__ Whc,
                         const float* __restrict__ Wxo, const float* __restrict__ Who) {
    if (blockIdx.x < 8192) {
        const size_t idx = (size_t)blockIdx.x * 256 + threadIdx.x;
        const int m = (int)(idx >> 9);
        const int k = (int)(idx & 511) * 8;
        const float* s = (k < 2048) ? x + (size_t)m * 2048 + k
                                    : h + (size_t)m * 2048 + (k - 2048);
        const float4 v0 = ((const float4*)s)[0];
        const float4 v1 = ((const float4*)s)[1];
        __half2 p0 = __floats2half2_rn(v0.x, v0.y);
        __half2 p1 = __floats2half2_rn(v0.z, v0.w);
        __half2 p2 = __floats2half2_rn(v1.x, v1.y);
        __half2 p3 = __floats2half2_rn(v1.z, v1.w);
        uint4 o;
        o.x = *(uint32_t*)&p0; o.y = *(uint32_t*)&p1;
        o.z = *(uint32_t*)&p2; o.w = *(uint32_t*)&p3;
        g_Ah4[idx] = o;
    } else {
        __shared__ float t[32][33];
        const float* Wx[4] = {Wxi, Wxf, Wxc, Wxo};
        const float* Wh[4] = {Whi, Whf, Whc, Who};
        const int b  = blockIdx.x - 8192;        // 0..8191 = 128 k-tiles x 64 n-tiles
        const int k0 = (b >> 6) * 32;            // 0..4064
        const int n0 = (b & 63) * 32;            // 0..2016
        const int tx = threadIdx.x & 31;
        const int ty = threadIdx.x >> 5;         // 0..7
        const int kk = k0 & 2047;
        __half* gW = (__half*)g_Wh4;
#pragma unroll
        for (int g = 0; g < 4; g++) {
            const float* src = (k0 < 2048) ? Wx[g] : Wh[g];
#pragma unroll
            for (int j = 0; j < 4; j++)
                t[ty + 8 * j][tx] = src[(size_t)(kk + ty + 8 * j) * NDIM + n0 + tx];
            __syncthreads();
#pragma unroll
            for (int j = 0; j < 4; j++)
                gW[((size_t)g * NDIM + n0 + ty + 8 * j) * KDIM + k0 + tx] =
                    __float2half_rn(t[tx][ty + 8 * j]);
            __syncthreads();
        }
    }
}

// ------------------------------ main kernel --------------------------------
__device__ __forceinline__ void load_stage(uint32_t st, int kb, int tid, int bm, int bn) {
    const __half* gA = (const __half*)g_Ah4;
    const __half* gW = (const __half*)g_Wh4;
#pragma unroll
    for (int i = 0; i < 10; i++) {
        const int ch = tid + i * 256;                 // 0..2559
        if (ch < 512) {                               // A: 64 rows x 8 chunks
            const int row = ch >> 3, c16 = ch & 7;
            const __half* src = gA + (size_t)(bm + row) * KDIM + kb + c16 * 8;
            CP_ASYNC16(st + SWZ(row * 128 + c16 * 16), src);
        } else {                                      // B: 4 gates x 64 rows x 8
            const int b = ch - 512;
            const int gg = b >> 9, bb = b & 511;
            const int row = bb >> 3, c16 = bb & 7;
            const __half* src = gW + ((size_t)gg * NDIM + bn + row) * KDIM + kb + c16 * 8;
            CP_ASYNC16(st + A_STAGE_BYTES + gg * BG_STAGE_BYTES + SWZ(row * 128 + c16 * 16), src);
        }
    }
    CP_COMMIT();
}

__global__ __launch_bounds__(THREADS, 2)
void lstm_fp16_kernel(const float* __restrict__ cx,
                      const float* __restrict__ bi, const float* __restrict__ bf_,
                      const float* __restrict__ bc, const float* __restrict__ bo,
                      float* __restrict__ out) {
    extern __shared__ char smem[];
    const uint32_t sbase = smem_u32_of(smem);

    const int tid  = threadIdx.x;
    const int lane = tid & 31;
    const int wid  = tid >> 5;
    const int g    = wid & 3;    // gate
    const int mh   = wid >> 2;   // m-half (rows 0-31 / 32-63)

    const int bn = blockIdx.x * BN;
    const int bm = blockIdx.y * BM;

    float acc[2][8][4];
#pragma unroll
    for (int t = 0; t < 2; t++)
#pragma unroll
        for (int j = 0; j < 8; j++)
#pragma unroll
            for (int q = 0; q < 4; q++) acc[t][j][q] = 0.0f;

    // per-lane ldmatrix geometry
    const int j8    = lane & 7;
    const int mm    = lane >> 3;
    const int mlo   = (mm & 1) * 8;
    const int khalf = (mm >> 1) * 16;
    const int S     = j8 << 4;
    const int rowA  = mh * 32 + mlo + j8;
    const int rowB  = mlo + j8;

    // prologue: fill both stages
    load_stage(sbase, 0, tid, bm, bn);
    load_stage(sbase + STAGE_BYTES, BK, tid, bm, bn);

    for (int kt = 0; kt < KT; kt++) {
        CP_WAIT1();
        __syncthreads();

        const uint32_t stA = sbase + (kt & 1) * STAGE_BYTES;
        const uint32_t stB = stA + A_STAGE_BYTES + g * BG_STAGE_BYTES;

#pragma unroll
        for (int ks = 0; ks < 4; ks++) {
            const int KX = (ks * 32 + khalf) ^ S;
            uint32_t a[2][4], b[4][4];
            LDSM_X4(a[0], stA + rowA * 128 + KX);
            LDSM_X4(a[1], stA + (rowA + 16) * 128 + KX);
#pragma unroll
            for (int p = 0; p < 4; p++)
                LDSM_X4(b[p], stB + (rowB + p * 16) * 128 + KX);
#pragma unroll
            for (int t = 0; t < 2; t++)
#pragma unroll
                for (int j = 0; j < 8; j++) {
                    const int p = j >> 1, o = j & 1;
                    mma16816(acc[t][j], a[t], b[p][o], b[p][o + 2]);
                }
        }
        __syncthreads();

        // load into the slot just consumed (safe after the barrier above)
        if (kt + 2 < KT) load_stage(sbase + (kt & 1) * STAGE_BYTES, (kt + 2) * BK, tid, bm, bn);
        else             CP_COMMIT();   // keep 2-outstanding invariant for WAIT1
    }

    // ---- epilogue: combine gates, activations, write hy/cy ----
    float* eps = (float*)smem;                 // [4][32][64] = 32 KB
    const size_t outCY = (size_t)MDIM * NDIM;
    const int r = lane >> 2;
    const int c = lane & 3;

#pragma unroll
    for (int ph = 0; ph < 2; ph++) {
        __syncthreads();
        if (mh == ph) {
#pragma unroll
            for (int t = 0; t < 2; t++) {
#pragma unroll
                for (int j = 0; j < 8; j++) {
                    const int row0 = t * 16 + r;
                    const int col0 = j * 8 + c * 2;
                    eps[(g * 32 + row0) * 64 + col0]         = acc[t][j][0];
                    eps[(g * 32 + row0) * 64 + col0 + 1]     = acc[t][j][1];
                    eps[(g * 32 + row0 + 8) * 64 + col0]     = acc[t][j][2];
                    eps[(g * 32 + row0 + 8) * 64 + col0 + 1] = acc[t][j][3];
                }
            }
        }
        __syncthreads();

        for (int idx = tid; idx < 32 * 64; idx += THREADS) {
            const int ml = idx >> 6;
            const int nl = idx & 63;
            const int gm = bm + ph * 32 + ml;
            const int gn = bn + nl;

            const float zi = eps[(0 * 32 + ml) * 64 + nl] + bi[gn];
            const float zf = eps[(1 * 32 + ml) * 64 + nl] + bf_[gn];
            const float zc = eps[(2 * 32 + ml) * 64 + nl] + bc[gn];
            const float zo = eps[(3 * 32 + ml) * 64 + nl] + bo[gn];

            const float ig = fast_sigmoid(zi);
            const float fg = fast_sigmoid(zf);
            const float og = fast_sigmoid(zo);
            const float ct = fast_tanh(zc);

            const float cprev = cx[(size_t)gm * NDIM + gn];
            const float cy = fg * cprev + ig * ct;
            const float hy = og * fast_tanh(cy);

            out[(size_t)gm * NDIM + gn] = hy;
            out[outCY + (size_t)gm * NDIM + gn] = cy;
        }
    }
}

// ------------------------------- launch ------------------------------------
extern "C" void kernel_launch(void* const* d_in, const int* in_sizes, int n_in,
                              void* d_out, int out_size) {
    (void)in_sizes; (void)n_in; (void)out_size;
    cudaFuncSetAttribute(lstm_fp16_kernel,
                         cudaFuncAttributeMaxDynamicSharedMemorySize, SMEM_TOTAL);

    prep_all<<<16384, 256>>>(
        (const float*)d_in[0],  (const float*)d_in[1],    // x, h_x
        (const float*)d_in[3],  (const float*)d_in[4],    // W_xi, W_hi
        (const float*)d_in[6],  (const float*)d_in[7],    // W_xf, W_hf
        (const float*)d_in[9],  (const float*)d_in[10],   // W_xc, W_hc
        (const float*)d_in[12], (const float*)d_in[13]);  // W_xo, W_ho

    dim3 grid(NDIM / BN, MDIM / BM);   // 32 x 64 = 2048 CTAs
    lstm_fp16_kernel<<<grid, THREADS, SMEM_TOTAL>>>(
        (const float*)d_in[2],                           // c_x
        (const float*)d_in[5],  (const float*)d_in[8],   // b_i, b_f
        (const float*)d_in[11], (const float*)d_in[14],  // b_c, b_o
        (float*)d_out);
}